// round 5
// baseline (speedup 1.0000x reference)
#include <cuda_runtime.h>
#include <cstddef>
#include <cstdint>
#include <math.h>

#define SEQ   512
#define BATCH 256
#define INP   256
#define HID   512

typedef unsigned long long u64;

// ---------- packed f32x2 helpers (sm_103a) ----------
__device__ __forceinline__ u64 dup2(float x) {
    u64 r; asm("mov.b64 %0,{%1,%1};" : "=l"(r) : "f"(x)); return r;
}
__device__ __forceinline__ void fma2(u64& d, u64 a, u64 b) {
    asm("fma.rn.f32x2 %0,%1,%2,%0;" : "+l"(d) : "l"(a), "l"(b));
}
__device__ __forceinline__ void add2(u64& d, u64 a) {
    asm("add.rn.f32x2 %0,%0,%1;" : "+l"(d) : "l"(a));
}
__device__ __forceinline__ float2 upk(u64 v) {
    float2 f; asm("mov.b64 {%0,%1},%2;" : "=f"(f.x), "=f"(f.y) : "l"(v)); return f;
}

// ---------- sync helpers ----------
__device__ __forceinline__ unsigned ld_acq(const unsigned* p) {
    unsigned v;
    asm volatile("ld.acquire.gpu.global.b32 %0,[%1];" : "=r"(v) : "l"(p) : "memory");
    return v;
}
__device__ __forceinline__ void st_rel(unsigned* p, unsigned v) {
    asm volatile("st.release.gpu.global.b32 [%0],%1;" :: "l"(p), "r"(v) : "memory");
}

// ---------- fast activations ----------
__device__ __forceinline__ float sig_f(float z) {
    return __fdividef(1.0f, 1.0f + __expf(-z));
}
__device__ __forceinline__ float tanh_f(float z) {
    return 1.0f - __fdividef(2.0f, __expf(2.0f * z) + 1.0f);
}

// ---------- scratch ----------
__device__ float g_xp[(size_t)SEQ * BATCH * 3 * HID];
__device__ float g_h[2][BATCH * HID];
__device__ unsigned g_flag[8][16];      // (batch group, j tile) -> step+1 published

__global__ void reset_kernel() {
    // zero all flags (replay safety)
    ((unsigned*)g_flag)[threadIdx.x] = 0u;
}

// ============================================================================
// Projection GEMM (unchanged): XP = X @ U^T + b for 3 weight sets.
// ============================================================================
__global__ void __launch_bounds__(256) proj_kernel(
    const float* __restrict__ X,
    const float* __restrict__ Uc, const float* __restrict__ bc,
    const float* __restrict__ Ua, const float* __restrict__ ba,
    const float* __restrict__ Uh, const float* __restrict__ bh)
{
    __shared__ __align__(16) float As[16][128];
    __shared__ __align__(16) float Bs[16][128];

    const int nt = blockIdx.x;
    const int mt = blockIdx.y;
    const int n0 = nt * 128, m0 = mt * 128;
    const int region = n0 >> 9;
    const float* __restrict__ U    = (region == 0) ? Uc : (region == 1 ? Ua : Uh);
    const float* __restrict__ bias = (region == 0) ? bc : (region == 1 ? ba : bh);
    const int nl0 = n0 & 511;

    const int tid = threadIdx.x;
    const int tn = tid & 15;
    const int tm = tid >> 4;
    const int lr = tid & 127;
    const int lc = tid >> 7;

    u64 acc[8][4];
    #pragma unroll
    for (int i = 0; i < 8; i++)
        #pragma unroll
        for (int q = 0; q < 4; q++) acc[i][q] = 0ull;

    for (int kt = 0; kt < 16; kt++) {
        const int k0 = kt * 16;
        #pragma unroll
        for (int half = 0; half < 2; half++) {
            int c = lc + 2 * half;
            float4 v = *(const float4*)&X[(size_t)(m0 + lr) * INP + k0 + c * 4];
            As[c * 4 + 0][lr] = v.x; As[c * 4 + 1][lr] = v.y;
            As[c * 4 + 2][lr] = v.z; As[c * 4 + 3][lr] = v.w;
        }
        #pragma unroll
        for (int half = 0; half < 2; half++) {
            int c = lc + 2 * half;
            float4 v = *(const float4*)&U[(size_t)(nl0 + lr) * INP + k0 + c * 4];
            Bs[c * 4 + 0][lr] = v.x; Bs[c * 4 + 1][lr] = v.y;
            Bs[c * 4 + 2][lr] = v.z; Bs[c * 4 + 3][lr] = v.w;
        }
        __syncthreads();

        #pragma unroll
        for (int k = 0; k < 16; k++) {
            float4 a0 = *(const float4*)&As[k][tm * 8];
            float4 a1 = *(const float4*)&As[k][tm * 8 + 4];
            ulonglong2 b0 = *(const ulonglong2*)&Bs[k][tn * 8];
            ulonglong2 b1 = *(const ulonglong2*)&Bs[k][tn * 8 + 4];
            u64 ad[8];
            ad[0] = dup2(a0.x); ad[1] = dup2(a0.y); ad[2] = dup2(a0.z); ad[3] = dup2(a0.w);
            ad[4] = dup2(a1.x); ad[5] = dup2(a1.y); ad[6] = dup2(a1.z); ad[7] = dup2(a1.w);
            #pragma unroll
            for (int i = 0; i < 8; i++) {
                fma2(acc[i][0], ad[i], b0.x);
                fma2(acc[i][1], ad[i], b0.y);
                fma2(acc[i][2], ad[i], b1.x);
                fma2(acc[i][3], ad[i], b1.y);
            }
        }
        __syncthreads();
    }

    float bv[8];
    #pragma unroll
    for (int q = 0; q < 8; q++) bv[q] = bias[nl0 + tn * 8 + q];
    #pragma unroll
    for (int i = 0; i < 8; i++) {
        const size_t m = (size_t)m0 + tm * 8 + i;
        float2 p0 = upk(acc[i][0]), p1 = upk(acc[i][1]);
        float2 p2 = upk(acc[i][2]), p3 = upk(acc[i][3]);
        float4 o0 = make_float4(p0.x + bv[0], p0.y + bv[1], p1.x + bv[2], p1.y + bv[3]);
        float4 o1 = make_float4(p2.x + bv[4], p2.y + bv[5], p3.x + bv[6], p3.y + bv[7]);
        float* dst = &g_xp[m * 1536 + n0 + tn * 8];
        *(float4*)dst       = o0;
        *(float4*)(dst + 4) = o1;
    }
}

// ============================================================================
// Recurrence v5: dataflow pipeline. No global counting barrier.
// Warp (ks,jh) polls ONE producer flag, stages its 32 h-columns, pairs via
// named barrier, runs matvec. Producers publish flags after epilogue.
// ============================================================================
#define HSTR 516

__global__ void __launch_bounds__(512, 1) recur_kernel(
    const float* __restrict__ h_in,
    const float* __restrict__ Wc, const float* __restrict__ Wa,
    float* __restrict__ out)
{
    extern __shared__ float sm[];
    float* Ws  = sm;                     // [512k][64]: [k][j]=Wc, [k][32+j]=Wa
    float* Hs  = sm + 32768;             // [32 b][HSTR]
    float* Red = sm + 32768 + 16512;     // partials
    ulonglong2* RedU = (ulonglong2*)Red;

    const int ct = blockIdx.x;           // 0..127
    const int jt = ct & 15, bt = ct >> 4;
    const int j0 = jt * 32, b0 = bt * 32;
    const int tid = threadIdx.x;
    const int w = tid >> 5, lane = tid & 31;
    const int ks = w >> 1, jh = w & 1;   // k-slice (8), j-half (2)
    const int jg = lane >> 3;
    const int bl = lane & 7;
    const int kw0 = ks * 64;
    const int jwl = jh * 16 + jg * 4;

    // consumer mapping: tid = b*16 + jp, j = jp*2 (+0,+1)
    const int cb  = tid >> 4;
    const int jp  = tid & 15;
    const int cjh = jp >> 3;
    const int cjg = (jp >> 1) & 3;
    const int cje = (jp & 1) * 2;
    const int ci  = cb >> 3, cbl = cb & 7;
    const int rbase = (((cjh * 8 + ci) * 32 + cbl * 4 + cjg) << 2) + cje;

    const int ksm = ks & 3;
    const int pbase = ((ksm * 2 + jh) * 8) * 32 + bl * 4 + jg;

    // this warp's staging region: 32 h-columns from producer jt' = 2ks+jh
    const int c0 = ks * 64 + jh * 32;
    const unsigned* myflag = &g_flag[bt][2 * ks + jh];

    // ---- stage weights (one-time) ----
    for (int idx = tid; idx < 32 * 128; idx += 512) {
        int j = idx >> 7, k = (idx & 127) << 2;
        float4 wc = __ldcg((const float4*)&Wc[(size_t)(j0 + j) * HID + k]);
        float4 wa = __ldcg((const float4*)&Wa[(size_t)(j0 + j) * HID + k]);
        Ws[(k + 0) * 64 + j] = wc.x; Ws[(k + 1) * 64 + j] = wc.y;
        Ws[(k + 2) * 64 + j] = wc.z; Ws[(k + 3) * 64 + j] = wc.w;
        Ws[(k + 0) * 64 + 32 + j] = wa.x; Ws[(k + 1) * 64 + 32 + j] = wa.y;
        Ws[(k + 2) * 64 + 32 + j] = wa.z; Ws[(k + 3) * 64 + 32 + j] = wa.w;
    }
    __syncthreads();

    for (int t = 0; t < SEQ; t++) {
        // prefetch input projections (consumer-mapped; overlaps poll+stage+matvec)
        const size_t crow = (size_t)t * BATCH + b0 + cb;
        const float* xpb = &g_xp[crow * 1536 + j0 + jp * 2];
        float2 xc = __ldcg((const float2*)(xpb));
        float2 xa = __ldcg((const float2*)(xpb + 512));
        float2 xh = __ldcg((const float2*)(xpb + 1024));

        // ---- per-warp: wait for my producer, stage my 32 h-columns ----
        const float* __restrict__ hsrc = (t == 0) ? h_in : g_h[t & 1];
        if (t > 0 && lane == 0) {
            while (ld_acq(myflag) < (unsigned)t) { }
        }
        __syncwarp();
        {
            const float* src = &hsrc[(size_t)(b0 + lane) * HID + c0];
            float* dst = &Hs[lane * HSTR + c0];
            #pragma unroll
            for (int q = 0; q < 8; q++) {
                float4 v = __ldcg((const float4*)(src + q * 4));
                *(float4*)(dst + q * 4) = v;
            }
        }
        // pair-sync with sibling warp (other half of this k-slice)
        asm volatile("bar.sync %0, 64;" :: "r"(1 + ks) : "memory");

        // ---- matvec over this warp's 64-k slice, 16j x 32b ----
        u64 acc[2][4][2];
        #pragma unroll
        for (int m = 0; m < 2; m++)
            #pragma unroll
            for (int i = 0; i < 4; i++) { acc[m][i][0] = 0ull; acc[m][i][1] = 0ull; }

        #pragma unroll 2
        for (int k4 = 0; k4 < 16; k4++) {
            const int kk = kw0 + k4 * 4;
            float4 hv[4];
            #pragma unroll
            for (int i = 0; i < 4; i++)
                hv[i] = *(const float4*)&Hs[(bl + 8 * i) * HSTR + kk];
            #pragma unroll
            for (int q = 0; q < 4; q++) {
                const float* wr = &Ws[(kk + q) * 64 + jwl];
                ulonglong2 wc = *(const ulonglong2*)wr;
                ulonglong2 wa = *(const ulonglong2*)(wr + 32);
                #pragma unroll
                for (int i = 0; i < 4; i++) {
                    float hq = (q == 0) ? hv[i].x : (q == 1) ? hv[i].y
                             : (q == 2) ? hv[i].z : hv[i].w;
                    u64 hd = dup2(hq);
                    fma2(acc[0][i][0], hd, wc.x); fma2(acc[0][i][1], hd, wc.y);
                    fma2(acc[1][i][0], hd, wa.x); fma2(acc[1][i][1], hd, wa.y);
                }
            }
        }

        // ---- round 1: k-slices 0-3 store partials ----
        if (ks < 4) {
            #pragma unroll
            for (int m = 0; m < 2; m++)
                #pragma unroll
                for (int i = 0; i < 4; i++)
                    RedU[pbase + (m * 4 + i) * 32] =
                        make_ulonglong2(acc[m][i][0], acc[m][i][1]);
        }
        __syncthreads();
        // ---- round 2: k-slices 4-7 accumulate in place ----
        if (ks >= 4) {
            #pragma unroll
            for (int m = 0; m < 2; m++)
                #pragma unroll
                for (int i = 0; i < 4; i++) {
                    const int idx = pbase + (m * 4 + i) * 32;
                    ulonglong2 v = RedU[idx];
                    add2(acc[m][i][0], v.x); add2(acc[m][i][1], v.y);
                    RedU[idx] = make_ulonglong2(acc[m][i][0], acc[m][i][1]);
                }
        }
        __syncthreads();

        // ---- consumer: sum 4 regions, fused gated epilogue, stores ----
        {
            float2 hc = make_float2(0.f, 0.f), ha = make_float2(0.f, 0.f);
            #pragma unroll
            for (int r = 0; r < 4; r++) {
                float2 vc = *(const float2*)&Red[rbase + r * 2048];
                float2 va = *(const float2*)&Red[rbase + r * 2048 + 512];
                hc.x += vc.x; hc.y += vc.y;
                ha.x += va.x; ha.y += va.y;
            }
            float2 hp = *(const float2*)&Hs[cb * HSTR + j0 + jp * 2];

            float r0, r1;
            {
                float cg = sig_f(xc.x + hc.x);
                float ag = 1.0f + tanh_f(xa.x + ha.x);
                r0 = cg * hp.x + (1.0f - cg) * tanh_f(xh.x + ag * hp.x);
            }
            {
                float cg = sig_f(xc.y + hc.y);
                float ag = 1.0f + tanh_f(xa.y + ha.y);
                r1 = cg * hp.y + (1.0f - cg) * tanh_f(xh.y + ag * hp.y);
            }
            float2 rv = make_float2(r0, r1);
            __stcg((float2*)&out[crow * HID + j0 + jp * 2], rv);
            __stcg((float2*)&g_h[(t + 1) & 1][(size_t)(b0 + cb) * HID + j0 + jp * 2], rv);
            if (t == SEQ - 1)
                __stcg((float2*)&out[(size_t)SEQ * BATCH * HID +
                                     (size_t)(b0 + cb) * HID + j0 + jp * 2], rv);
        }

        // ---- publish: my h(t) slice is ready ----
        __syncthreads();
        if (tid == 0) {
            __threadfence();
            st_rel(&g_flag[bt][jt], (unsigned)(t + 1));
        }
    }
}

// ============================================================================
extern "C" void kernel_launch(void* const* d_in, const int* in_sizes, int n_in,
                              void* d_out, int out_size)
{
    const float* X  = (const float*)d_in[0];
    const float* h0 = (const float*)d_in[1];
    const float* Uc = (const float*)d_in[2];
    const float* Wc = (const float*)d_in[3];
    const float* bc = (const float*)d_in[4];
    const float* Ua = (const float*)d_in[5];
    const float* Wa = (const float*)d_in[6];
    const float* ba = (const float*)d_in[7];
    const float* Uh = (const float*)d_in[8];
    const float* bh = (const float*)d_in[9];
    float* out = (float*)d_out;

    const size_t shmem = (size_t)(32768 + 16512 + 8192) * sizeof(float); // 229888 B
    cudaFuncSetAttribute(recur_kernel, cudaFuncAttributeMaxDynamicSharedMemorySize,
                         (int)shmem);

    reset_kernel<<<1, 128>>>();
    dim3 pg(12, 1024);
    proj_kernel<<<pg, 256>>>(X, Uc, bc, Ua, ba, Uh, bh);
    recur_kernel<<<128, 512, shmem>>>(h0, Wc, Wa, out);
}